// round 10
// baseline (speedup 1.0000x reference)
#include <cuda_runtime.h>

#define NPOINTS     500000
#define NWAVE       128
#define NOFFSETS    50

#define TPB         128
#define NBLK        1480            // 10 blocks/SM on 148 SMs
#define TILE        512             // >= max per-block count (338): ONE tile per block
#define QUOT        337             // NPOINTS / NBLK
#define REMR        1240            // NPOINTS - QUOT*NBLK

#define RB          128             // stage-2 grid
#define TWO_PI      6.283185307179586f

// Accum-native layout [block][wave].
__device__ float g_partialC[NBLK * NWAVE];
__device__ float g_partialS[NBLK * NWAVE];
// Stage-2 output [RB][wave].
__device__ float g2C[RB * NWAVE];
__device__ float g2S[RB * NWAVE];

__global__ __launch_bounds__(TPB, 10)
void accum_kernel(const float2* __restrict__ xy,
                  const float*  __restrict__ tid,
                  const float*  __restrict__ center,
                  const float*  __restrict__ wavelength)
{
    __shared__ float sdist[TILE];

    const int w  = threadIdx.x;
    const float kw = TWO_PI / wavelength[w];
    const float cx = center[0];
    const float cy = center[1];

    // Balanced contiguous range: blocks differ by at most 1 point of work.
    const int b    = blockIdx.x;
    const int base = b * QUOT + min(b, REMR);
    const int n    = QUOT + (b < REMR ? 1 : 0);     // 337 or 338, fits one tile

    // Phase A: cooperatively compute dist for ALL of this block's points.
    for (int k = threadIdx.x; k < n; k += TPB) {
        const float2 v = xy[base + k];
        const float dx = v.x - cx;
        const float dy = v.y - cy;
        sdist[k] = sqrtf(fmaf(dx, dx, dy * dy));
    }
    __syncthreads();                                 // the ONLY barrier

    // Phase B: sweep all points for this thread's wavelength.
    const float* __restrict__ trow = tid + (size_t)base * NWAVE + w;
    const float4* __restrict__ sdist4 = (const float4*)sdist;

    float accC = 0.0f;
    float accS = 0.0f;

    const int n4 = n >> 2;
    #pragma unroll 2
    for (int j = 0; j < n4; j++) {
        const float4 d4 = sdist4[j];                 // 1 LDS.128 per 4 points
        const size_t i0 = (size_t)(4 * j) * NWAVE;
        const float t0 = __ldcs(trow + i0);
        const float t1 = __ldcs(trow + i0 + NWAVE);
        const float t2 = __ldcs(trow + i0 + 2 * NWAVE);
        const float t3 = __ldcs(trow + i0 + 3 * NWAVE);

        float s, c;
        __sincosf(d4.x * kw, &s, &c); accC = fmaf(c, t0, accC); accS = fmaf(s, t0, accS);
        __sincosf(d4.y * kw, &s, &c); accC = fmaf(c, t1, accC); accS = fmaf(s, t1, accS);
        __sincosf(d4.z * kw, &s, &c); accC = fmaf(c, t2, accC); accS = fmaf(s, t2, accS);
        __sincosf(d4.w * kw, &s, &c); accC = fmaf(c, t3, accC); accS = fmaf(s, t3, accS);
    }
    for (int i = 4 * n4; i < n; i++) {               // 1-2 remainder points
        const float t = __ldcs(trow + (size_t)i * NWAVE);
        float s, c;
        __sincosf(sdist[i] * kw, &s, &c);
        accC = fmaf(c, t, accC);
        accS = fmaf(s, t, accS);
    }

    g_partialC[b * NWAVE + w] = accC;    // coalesced row store
    g_partialS[b * NWAVE + w] = accS;
}

// Stage 2: plain kernel, no atomics. Mapping (w = t&127, g = t>>7): a warp's
// lanes span 32 consecutive wavelengths of one row -> fully coalesced
// against [block][wave].
__global__ __launch_bounds__(256)
void reduce1_kernel()
{
    __shared__ float smC[2][NWAVE];
    __shared__ float smS[2][NWAVE];

    const int w = threadIdx.x & (NWAVE - 1);
    const int g = threadIdx.x >> 7;

    float c = 0.0f, s = 0.0f;
    #pragma unroll 6
    for (int b = blockIdx.x * 2 + g; b < NBLK; b += RB * 2) {  // fixed order
        c += g_partialC[b * NWAVE + w];
        s += g_partialS[b * NWAVE + w];
    }
    smC[g][w] = c;
    smS[g][w] = s;
    __syncthreads();

    if (g == 0) {
        g2C[blockIdx.x * NWAVE + w] = smC[0][w] + smC[1][w];   // coalesced
        g2S[blockIdx.x * NWAVE + w] = smS[0][w] + smS[1][w];
    }
}

// Stage 3: single block, 256 threads (2 groups of 128), each group sums 64
// L2-hot rows; combine, offset-max epilogue, tree-sum, negate.
__global__ __launch_bounds__(256)
void reduce2_kernel(float* __restrict__ out)
{
    __shared__ float smC[2][NWAVE];
    __shared__ float smS[2][NWAVE];
    __shared__ float smM[NWAVE];

    const int w = threadIdx.x & (NWAVE - 1);
    const int g = threadIdx.x >> 7;

    float c = 0.0f, s = 0.0f;
    #pragma unroll 8
    for (int r = g; r < RB; r += 2) {            // 64 coalesced loads each
        c += g2C[r * NWAVE + w];
        s += g2S[r * NWAVE + w];
    }
    smC[g][w] = c;
    smS[g][w] = s;
    __syncthreads();

    if (g == 0) {
        const float C = (smC[0][w] + smC[1][w]) * (1.0f / (float)NPOINTS);
        const float S = (smS[0][w] + smS[1][w]) * (1.0f / (float)NPOINTS);

        float m = -3.402823466e38f;
        #pragma unroll
        for (int i = 0; i < NOFFSETS; i++) {
            const float o = (float)i * (TWO_PI / (float)(NOFFSETS - 1));
            const float v = C * cosf(o) - S * sinf(o);
            m = fmaxf(m, v);
        }
        smM[w] = m;
    }
    __syncthreads();

    #pragma unroll
    for (int stride = NWAVE / 2; stride > 0; stride >>= 1) {
        if (threadIdx.x < stride) smM[threadIdx.x] += smM[threadIdx.x + stride];
        __syncthreads();
    }
    if (threadIdx.x == 0) out[0] = -smM[0];
}

extern "C" void kernel_launch(void* const* d_in, const int* in_sizes, int n_in,
                              void* d_out, int out_size)
{
    const float2* xy         = (const float2*)d_in[0];  // [500000, 2]
    const float*  tid        = (const float*) d_in[1];  // [500000, 128]
    const float*  center     = (const float*) d_in[2];  // [2]
    const float*  wavelength = (const float*) d_in[3];  // [128]
    float* out = (float*)d_out;

    accum_kernel<<<NBLK, TPB>>>(xy, tid, center, wavelength);
    reduce1_kernel<<<RB, 256>>>();
    reduce2_kernel<<<1, 256>>>(out);
}